// round 15
// baseline (speedup 1.0000x reference)
#include <cuda_runtime.h>
#include <cuda_fp16.h>
#include <cstdint>

#define BSZ 32
#define CIc 32
#define PP  256

__device__ short g_votes[BSZ*32*CIc*8*PP];   // [b][co][ci][p][no], value*256 (exact)
__device__ float g_logits[BSZ*CIc*32*PP];    // [b][ci][co][p]
__device__ float g_smax[BSZ*CIc];
__device__ float g_ssum[BSZ*CIc];
__device__ float g_thr[BSZ*CIc];             // r>=1 threshold: M + ln(S/512) - margin
__device__ uint4  g_wsplit[5632];            // W fp16 hi[0..45056) lo[45056..90112), 176B rows
__device__ __half g_xh[BSZ*CIc*2048];        // x fp16 hi
__device__ __half g_xl[BSZ*CIc*2048];        // x fp16 lo

// ---------------- helpers ----------------
static __device__ __forceinline__ uint32_t smem_u32(const void* p) {
    uint32_t a;
    asm("{ .reg .u64 t; cvta.to.shared.u64 t, %1; cvt.u32.u64 %0, t; }" : "=r"(a) : "l"(p));
    return a;
}

#define MMA16816(d, a, b) \
    asm volatile("mma.sync.aligned.m16n8k16.row.col.f32.f16.f16.f32 " \
        "{%0,%1,%2,%3}, {%4,%5,%6,%7}, {%8,%9}, {%0,%1,%2,%3};" \
        : "+f"((d)[0]), "+f"((d)[1]), "+f"((d)[2]), "+f"((d)[3]) \
        : "r"((a)[0]), "r"((a)[1]), "r"((a)[2]), "r"((a)[3]), "r"((b)[0]), "r"((b)[1]))

#define MMA1688(d, a0, a1, b0) \
    asm volatile("mma.sync.aligned.m16n8k8.row.col.f32.f16.f16.f32 " \
        "{%0,%1,%2,%3}, {%4,%5}, {%6}, {%0,%1,%2,%3};" \
        : "+f"((d)[0]), "+f"((d)[1]), "+f"((d)[2]), "+f"((d)[3]) \
        : "r"(a0), "r"(a1), "r"(b0))

#define LDMX4(r0, r1, r2, r3, addr) \
    asm volatile("ldmatrix.sync.aligned.m8n8.x4.shared.b16 {%0,%1,%2,%3}, [%4];" \
        : "=r"(r0), "=r"(r1), "=r"(r2), "=r"(r3) : "r"(addr))

static __device__ __forceinline__ uint32_t packh(__half a, __half b) {
    return (uint32_t)__half_as_ushort(a) | ((uint32_t)__half_as_ushort(b) << 16);
}
static __device__ __forceinline__ uint32_t packsplit(float f0, float f1, uint32_t &lo) {
    __half h0 = __float2half_rn(f0), h1 = __float2half_rn(f1);
    __half l0 = __float2half_rn(__fsub_rn(f0, __half2float(h0)));
    __half l1 = __float2half_rn(__fsub_rn(f1, __half2float(h1)));
    lo = packh(l0, l1);
    return packh(h0, h1);
}
static __device__ __forceinline__ void upk(uint32_t u, int &a, int &b) {
    a = (int)(short)(u & 0xFFFFu);
    b = ((int)u) >> 16;
}

// 176B rows: 44*i mod 32 covers all banks -> ldmatrix conflict-free
#define ROWB       176u
#define BHI_OFF    0u
#define BLO_OFF    45056u
#define AHI_OFF    90112u
#define ALO_OFF    135168u
#define XSH_OFF    180224u
#define XSL_OFF    185408u
#define CBS_OFF    190592u
#define A1S_OFF    191616u
#define KLUT_OFF   192640u
#define CONV_SMEM  192928

// ---------------------------------------------------------------------------
// Prep: x -> fp16 hi/lo per tile; block 0 additionally splits W (layout-final)
// ---------------------------------------------------------------------------
__global__ void __launch_bounds__(256) prep_kernel(
    const float* __restrict__ x, const float* __restrict__ w)
{
    const int tile = blockIdx.x;           // b*32 + ci
    const float4* src = (const float4*)(x + tile*2048);
    #pragma unroll
    for (int i = 0; i < 2; i++) {
        int idx4 = threadIdx.x + i*256;
        float4 v = src[idx4];
        uint32_t l0, l1;
        uint32_t h0 = packsplit(v.x, v.y, l0);
        uint32_t h1 = packsplit(v.z, v.w, l1);
        *(uint2*)(g_xh + tile*2048 + idx4*4) = make_uint2(h0, h1);
        *(uint2*)(g_xl + tile*2048 + idx4*4) = make_uint2(l0, l1);
    }
    if (blockIdx.x == 0) {
        const int o = threadIdx.x;
        const float4* wr = (const float4*)(w + o*72);
        char* bh = (char*)g_wsplit + o*ROWB;
        char* bl = (char*)g_wsplit + 45056 + o*ROWB;
        #pragma unroll
        for (int q = 0; q < 18; q++) {
            float4 v = wr[q];
            uint32_t l0, l1;
            uint32_t h0 = packsplit(v.x, v.y, l0);
            uint32_t h1 = packsplit(v.z, v.w, l1);
            *(uint2*)(bh + q*8) = make_uint2(h0, h1);
            *(uint2*)(bl + q*8) = make_uint2(l0, l1);
        }
        *(uint4*)(bh + 144) = make_uint4(0,0,0,0);
        *(uint4*)(bh + 160) = make_uint4(0,0,0,0);
        *(uint4*)(bl + 144) = make_uint4(0,0,0,0);
        *(uint4*)(bl + 160) = make_uint4(0,0,0,0);
    }
}

// ---------------------------------------------------------------------------
// Kernel 1: fp16-split mma.sync conv -> int16 votes + iteration-1 logits.
// block = (b, ci), 512 threads / 16 warps. Votes [b][co][ci][p][no].
// ---------------------------------------------------------------------------
__global__ void __launch_bounds__(512, 1) conv_votes_kernel(
    const float* __restrict__ cb, const float* __restrict__ bias)
{
    extern __shared__ char sh[];
    float* cbs = (float*)(sh + CBS_OFF);
    int*   a1s = (int*)(sh + A1S_OFF);
    int*   klut= (int*)(sh + KLUT_OFF);
    const uint32_t smb = smem_u32(sh);

    const int t = threadIdx.x;
    const int wid = t >> 5, lane = t & 31;
    const int b = blockIdx.x >> 5, ci = blockIdx.x & 31;

    {
        const uint4* src = g_wsplit;
        uint4* dst = (uint4*)sh;
        #pragma unroll
        for (int i = 0; i < 11; i++) dst[t + i*512] = src[t + i*512];
    }
    {
        uint32_t* z = (uint32_t*)(sh + XSH_OFF);
        #pragma unroll
        for (int i = 0; i < 6; i++) {
            int idx = t + i*512;
            if (idx < 2592) z[idx] = 0;
        }
    }
    if (t < 256) cbs[t] = cb[t];
    if (t < 72) { int ni = t/9, r = t%9; klut[t] = ni*324 + (r/3)*18 + (r%3); }
    if (t < 32) {
        float pv[8]; float ss = 0.f;
        #pragma unroll
        for (int no = 0; no < 8; no++) {
            float q = rintf(__fmul_rn(bias[t*8+no], 256.f)) * 0.00390625f;
            pv[no] = q; ss = __fadd_rn(ss, __fmul_rn(q, q));
        }
        float n = sqrtf(ss);
        float den = __fadd_rn(1.f, __fmul_rn(n, n));
        #pragma unroll
        for (int no = 0; no < 8; no++) {
            float a = __fdiv_rn(__fmul_rn(pv[no], n), den);
            a1s[t*8+no] = __float2int_rn(__fmul_rn(a, 256.f));
        }
    }
    __syncthreads();

    {
        const __half* xh = g_xh + blockIdx.x*2048;
        const __half* xl = g_xl + blockIdx.x*2048;
        unsigned short* dh = (unsigned short*)(sh + XSH_OFF);
        unsigned short* dl = (unsigned short*)(sh + XSL_OFF);
        #pragma unroll
        for (int i = 0; i < 4; i++) {
            int idx = t + i*512;
            int ni = idx >> 8, rem = idx & 255;
            int dsto = ni*324 + ((rem>>4)+1)*18 + (rem&15) + 1;
            dh[dsto] = __half_as_ushort(xh[idx]);
            dl[dsto] = __half_as_ushort(xl[idx]);
        }
    }
    __syncthreads();
    {
        const int p = t & 255;
        const unsigned short* xsrc = (unsigned short*)(sh + ((t < 256) ? XSH_OFF : XSL_OFF));
        char* dst = sh + ((t < 256) ? AHI_OFF : ALO_OFF) + p*ROWB;
        const int xyb = (p >> 4)*18 + (p & 15);
        #pragma unroll
        for (int q = 0; q < 9; q++) {
            uint32_t u[4];
            #pragma unroll
            for (int j = 0; j < 4; j++) {
                uint32_t v0 = xsrc[klut[q*8 + 2*j]     + xyb];
                uint32_t v1 = xsrc[klut[q*8 + 2*j + 1] + xyb];
                u[j] = v0 | (v1 << 16);
            }
            *(uint4*)(dst + q*16) = make_uint4(u[0], u[1], u[2], u[3]);
        }
        *(uint4*)(dst + 144) = make_uint4(0,0,0,0);
        *(uint4*)(dst + 160) = make_uint4(0,0,0,0);
    }
    __syncthreads();

    const int pbase = (wid & 7)*32;
    const int obase = (wid >> 3)*128;
    const int lane2 = (lane & 3)*2;

    #pragma unroll 1
    for (int pass = 0; pass < 4; pass++) {
        const int otile = obase + pass*32;
        float acc[2][4][4];
        #pragma unroll
        for (int mt = 0; mt < 2; mt++)
            #pragma unroll
            for (int nt = 0; nt < 4; nt++)
                #pragma unroll
                for (int j = 0; j < 4; j++) acc[mt][nt][j] = 0.f;

        #pragma unroll
        for (int kc = 0; kc < 5; kc++) {
            uint32_t ah[2][4], al[2][4];
            #pragma unroll
            for (int mt = 0; mt < 2; mt++) {
                const uint32_t arow = pbase + mt*16 + (lane & 15);
                const uint32_t aoff = arow*ROWB + kc*32 + ((lane >> 4) << 4);
                LDMX4(ah[mt][0], ah[mt][1], ah[mt][2], ah[mt][3], smb + AHI_OFF + aoff);
                LDMX4(al[mt][0], al[mt][1], al[mt][2], al[mt][3], smb + ALO_OFF + aoff);
            }
            uint32_t bh[4][2], bl[4][2];
            #pragma unroll
            for (int g = 0; g < 2; g++) {
                const uint32_t row = otile + g*16 + (lane & 7) + ((lane >> 4) << 3);
                const uint32_t koff = kc*32 + ((lane >> 3) & 1)*16;
                LDMX4(bh[2*g][0], bh[2*g][1], bh[2*g+1][0], bh[2*g+1][1],
                      smb + BHI_OFF + row*ROWB + koff);
                LDMX4(bl[2*g][0], bl[2*g][1], bl[2*g+1][0], bl[2*g+1][1],
                      smb + BLO_OFF + row*ROWB + koff);
            }
            if (kc < 4) {
                #pragma unroll
                for (int mt = 0; mt < 2; mt++)
                    #pragma unroll
                    for (int nt = 0; nt < 4; nt++)
                        MMA16816(acc[mt][nt], ah[mt], bh[nt]);
                #pragma unroll
                for (int mt = 0; mt < 2; mt++)
                    #pragma unroll
                    for (int nt = 0; nt < 4; nt++)
                        MMA16816(acc[mt][nt], ah[mt], bl[nt]);
                #pragma unroll
                for (int mt = 0; mt < 2; mt++)
                    #pragma unroll
                    for (int nt = 0; nt < 4; nt++)
                        MMA16816(acc[mt][nt], al[mt], bh[nt]);
            } else {
                #pragma unroll
                for (int mt = 0; mt < 2; mt++)
                    #pragma unroll
                    for (int nt = 0; nt < 4; nt++)
                        MMA1688(acc[mt][nt], ah[mt][0], ah[mt][1], bh[nt][0]);
                #pragma unroll
                for (int mt = 0; mt < 2; mt++)
                    #pragma unroll
                    for (int nt = 0; nt < 4; nt++)
                        MMA1688(acc[mt][nt], ah[mt][0], ah[mt][1], bl[nt][0]);
                #pragma unroll
                for (int mt = 0; mt < 2; mt++)
                    #pragma unroll
                    for (int nt = 0; nt < 4; nt++)
                        MMA1688(acc[mt][nt], al[mt][0], al[mt][1], bh[nt][0]);
            }
        }

        // epilogue: votes [ci][p][no] (u32 pair stores) + quad-shuffle logit fold
        #pragma unroll
        for (int mt = 0; mt < 2; mt++) {
            const int p0 = pbase + mt*16 + (lane >> 2);
            #pragma unroll
            for (int nt = 0; nt < 4; nt++) {
                const int o = otile + nt*8 + lane2;     // no = lane2 (even), co = o>>3
                const float cb0 = cbs[o], cb1 = cbs[o+1];
                int v0 = __float2int_rn((acc[mt][nt][0] + cb0) * 256.f);
                int v1 = __float2int_rn((acc[mt][nt][1] + cb1) * 256.f);
                int v2 = __float2int_rn((acc[mt][nt][2] + cb0) * 256.f);
                int v3 = __float2int_rn((acc[mt][nt][3] + cb1) * 256.f);
                short* vb = g_votes + ((size_t)b << 21) + ((o >> 3)*32 + ci)*2048;
                *(uint32_t*)(vb + p0*8 + lane2)       = (v0 & 0xFFFF) | ((uint32_t)v1 << 16);
                *(uint32_t*)(vb + (p0 + 8)*8 + lane2) = (v2 & 0xFFFF) | ((uint32_t)v3 << 16);
                int s0 = a1s[o]*v0 + a1s[o+1]*v1;
                int s1 = a1s[o]*v2 + a1s[o+1]*v3;
                s0 += __shfl_xor_sync(0xffffffffu, s0, 1);
                s0 += __shfl_xor_sync(0xffffffffu, s0, 2);
                s1 += __shfl_xor_sync(0xffffffffu, s1, 1);
                s1 += __shfl_xor_sync(0xffffffffu, s1, 2);
                if ((lane & 3) == 0) {
                    float* lb = g_logits + ((b*32 + ci)*32 + (o >> 3))*256;
                    lb[p0]     = rintf((float)s0 * 0.00390625f) * 0.00390625f;
                    lb[p0 + 8] = rintf((float)s1 * 0.00390625f) * 0.00390625f;
                }
            }
        }
    }
}

// ---------------------------------------------------------------------------
// Kernel 2: softmax stats per (b, ci) over 8192 logits (+ r>=1 threshold)
// ---------------------------------------------------------------------------
__global__ void __launch_bounds__(256) softmax_kernel()
{
    const int row = blockIdx.x;
    const float* lp = g_logits + row*8192;
    const int t = threadIdx.x;
    float fl[32];
    #pragma unroll
    for (int i = 0; i < 32; i++) fl[i] = lp[i*256 + t];
    float m = fl[0];
    #pragma unroll
    for (int i = 1; i < 32; i++) m = fmaxf(m, fl[i]);
    __shared__ float red[8];
    #pragma unroll
    for (int off = 16; off; off >>= 1) m = fmaxf(m, __shfl_xor_sync(0xffffffffu, m, off));
    if ((t & 31) == 0) red[t >> 5] = m;
    __syncthreads();
    float M = red[0];
    #pragma unroll
    for (int i = 1; i < 8; i++) M = fmaxf(M, red[i]);
    __syncthreads();
    float s = 0.f;
    #pragma unroll
    for (int i = 0; i < 32; i++) s += expf(fl[i] - M);
    #pragma unroll
    for (int off = 16; off; off >>= 1) s += __shfl_xor_sync(0xffffffffu, s, off);
    if ((t & 31) == 0) red[t >> 5] = s;
    __syncthreads();
    if (t == 0) {
        float S = red[0];
        for (int i = 1; i < 8; i++) S += red[i];
        g_smax[row] = M;
        g_ssum[row] = S;
        // r >= 1 requires 256*e^(lv-M)/S > 0.5  <=>  lv >= M + ln(S/512).
        g_thr[row] = M + logf(S * 0.001953125f) - 1e-3f;
    }
}

// ---------------------------------------------------------------------------
// Kernel 3: fused routing iteration. block = (bco, ph); 512 threads =
// (p 0..127) x (c-quarter 0..3). Each quarter walks 8 c's; exact-int partial
// S reduced via smem (order-invariant) -> bit-identical, 1/4 the serial
// chain per warp. out written only on the last iteration (iter-2's value is
// consumed solely as ai for distances; final launch overwrites all of out).
// ---------------------------------------------------------------------------
__global__ void __launch_bounds__(512) route_kernel(
    const float* __restrict__ bias, float* __restrict__ out, int last)
{
    __shared__ float smaxs[32], ssums[32], sthr[32], sb[8];
    __shared__ int sS[4][128][8];    // partial S per (cquarter, p, no)
    __shared__ int sai[128][8];      // activation ints per (p, no)

    const int t   = threadIdx.x;
    const int th  = t & 127;         // p index within half
    const int cq  = t >> 7;          // c-quarter (8 c's each)
    const int blk = blockIdx.x;
    const int bco = blk >> 1, ph = blk & 1;
    const int b   = bco >> 5, co = bco & 31;

    if (t < 32) {
        smaxs[t] = g_smax[b*32 + t];
        ssums[t] = g_ssum[b*32 + t];
        sthr[t]  = g_thr[b*32 + t];
    }
    if (t < 8)  sb[t] = bias[co*8 + t];
    __syncthreads();

    const uint4* vbase = (const uint4*)(g_votes + (size_t)bco*65536) + ph*128 + th;
    const float* lgp = g_logits + (size_t)(b*32 + cq*8)*8192 + co*256 + ph*128 + th;

    float l[8];
    int S[8] = {0,0,0,0,0,0,0,0};
    #pragma unroll
    for (int i = 0; i < 8; i++) {
        const int c = cq*8 + i;
        float lv = lgp[i*8192];
        l[i] = lv;
        if (lv >= sthr[c]) {      // only here can r >= 1 (guaranteed otherwise 0)
            float e = expf(lv - smaxs[c]);
            int r = __float2int_rn(__fmul_rn(__fdiv_rn(e, ssums[c]), 256.f));
            if (r) {
                uint4 vv = vbase[c*256];
                int e0, e1;
                upk(vv.x, e0, e1); S[0] += r*e0; S[1] += r*e1;
                upk(vv.y, e0, e1); S[2] += r*e0; S[3] += r*e1;
                upk(vv.z, e0, e1); S[4] += r*e0; S[5] += r*e1;
                upk(vv.w, e0, e1); S[6] += r*e0; S[7] += r*e1;
            }
        }
    }
    #pragma unroll
    for (int no = 0; no < 8; no++) sS[cq][th][no] = S[no];
    __syncthreads();

    if (cq == 0) {
        float pq[8]; float ss = 0.f;
        #pragma unroll
        for (int no = 0; no < 8; no++) {
            int St = sS[0][th][no] + sS[1][th][no] + sS[2][th][no] + sS[3][th][no];
            float pre = __fadd_rn(__fmul_rn((float)St, 1.52587890625e-05f), sb[no]);
            float q = rintf(__fmul_rn(pre, 256.f)) * 0.00390625f;
            pq[no] = q; ss = __fadd_rn(ss, __fmul_rn(q, q));
        }
        float n   = sqrtf(ss);
        float den = __fadd_rn(1.f, __fmul_rn(n, n));
        #pragma unroll
        for (int no = 0; no < 8; no++) {
            float a = __fdiv_rn(__fmul_rn(pq[no], n), den);
            int q = __float2int_rn(__fmul_rn(a, 256.f));
            sai[th][no] = q;
            if (last)
                out[(bco*8 + no)*256 + ph*128 + th] = (float)q * 0.00390625f;
        }
    }
    __syncthreads();

    if (!last) {
        int ai[8];
        #pragma unroll
        for (int no = 0; no < 8; no++) ai[no] = sai[th][no];
        float* lw = g_logits + (size_t)(b*32 + cq*8)*8192 + co*256 + ph*128 + th;
        #pragma unroll
        for (int i = 0; i < 8; i++) {
            const int c = cq*8 + i;
            uint4 vv = vbase[c*256];
            int e0, e1, m = 0;
            upk(vv.x, e0, e1); m += ai[0]*e0 + ai[1]*e1;
            upk(vv.y, e0, e1); m += ai[2]*e0 + ai[3]*e1;
            upk(vv.z, e0, e1); m += ai[4]*e0 + ai[5]*e1;
            upk(vv.w, e0, e1); m += ai[6]*e0 + ai[7]*e1;
            float lg = __fadd_rn(l[i], __fmul_rn((float)m, 1.52587890625e-05f));
            lw[i*8192] = rintf(__fmul_rn(lg, 256.f)) * 0.00390625f;
        }
    }
}

// ---------------------------------------------------------------------------
extern "C" void kernel_launch(void* const* d_in, const int* in_sizes, int n_in,
                              void* d_out, int out_size)
{
    const float* x    = (const float*)d_in[0];
    const float* w    = (const float*)d_in[1];
    const float* cb   = (const float*)d_in[2];
    const float* bias = (const float*)d_in[3];
    float* out = (float*)d_out;
    (void)in_sizes; (void)n_in; (void)out_size;

    cudaFuncSetAttribute(conv_votes_kernel, cudaFuncAttributeMaxDynamicSharedMemorySize, CONV_SMEM);

    prep_kernel<<<1024, 256>>>(x, w);                         // launch 1 (W + x split)
    conv_votes_kernel<<<1024, 512, CONV_SMEM>>>(cb, bias);    // launch 2 (+ iter 1 folded)
    softmax_kernel<<<1024, 256>>>();                          // launch 3 (iteration 2)
    route_kernel<<<2048, 512>>>(bias, out, 0);                // launch 4 -> profiled
    softmax_kernel<<<1024, 256>>>();                          // iteration 3
    route_kernel<<<2048, 512>>>(bias, out, 1);
}

// round 16
// speedup vs baseline: 1.5372x; 1.5372x over previous
#include <cuda_runtime.h>
#include <cuda_fp16.h>
#include <cstdint>

#define BSZ 32
#define CIc 32
#define PP  256

__device__ short g_votes[BSZ*32*CIc*8*PP];   // [b][co][ci][p][no], value*256 (exact)
__device__ float g_logits[BSZ*CIc*32*PP];    // [b][ci][co][p]
__device__ float g_smax[BSZ*CIc];
__device__ float g_ssum[BSZ*CIc];
__device__ float g_thr[BSZ*CIc];             // r>=1 threshold: M + ln(S/512) - margin
__device__ uint4  g_wsplit[5632];            // W fp16 hi[0..45056) lo[45056..90112), 176B rows
__device__ __half g_xh[BSZ*CIc*2048];        // x fp16 hi
__device__ __half g_xl[BSZ*CIc*2048];        // x fp16 lo

// ---------------- helpers ----------------
static __device__ __forceinline__ uint32_t smem_u32(const void* p) {
    uint32_t a;
    asm("{ .reg .u64 t; cvta.to.shared.u64 t, %1; cvt.u32.u64 %0, t; }" : "=r"(a) : "l"(p));
    return a;
}

#define MMA16816(d, a, b) \
    asm volatile("mma.sync.aligned.m16n8k16.row.col.f32.f16.f16.f32 " \
        "{%0,%1,%2,%3}, {%4,%5,%6,%7}, {%8,%9}, {%0,%1,%2,%3};" \
        : "+f"((d)[0]), "+f"((d)[1]), "+f"((d)[2]), "+f"((d)[3]) \
        : "r"((a)[0]), "r"((a)[1]), "r"((a)[2]), "r"((a)[3]), "r"((b)[0]), "r"((b)[1]))

#define MMA1688(d, a0, a1, b0) \
    asm volatile("mma.sync.aligned.m16n8k8.row.col.f32.f16.f16.f32 " \
        "{%0,%1,%2,%3}, {%4,%5}, {%6}, {%0,%1,%2,%3};" \
        : "+f"((d)[0]), "+f"((d)[1]), "+f"((d)[2]), "+f"((d)[3]) \
        : "r"(a0), "r"(a1), "r"(b0))

#define LDMX4(r0, r1, r2, r3, addr) \
    asm volatile("ldmatrix.sync.aligned.m8n8.x4.shared.b16 {%0,%1,%2,%3}, [%4];" \
        : "=r"(r0), "=r"(r1), "=r"(r2), "=r"(r3) : "r"(addr))

static __device__ __forceinline__ uint32_t packh(__half a, __half b) {
    return (uint32_t)__half_as_ushort(a) | ((uint32_t)__half_as_ushort(b) << 16);
}
static __device__ __forceinline__ uint32_t packsplit(float f0, float f1, uint32_t &lo) {
    __half h0 = __float2half_rn(f0), h1 = __float2half_rn(f1);
    __half l0 = __float2half_rn(__fsub_rn(f0, __half2float(h0)));
    __half l1 = __float2half_rn(__fsub_rn(f1, __half2float(h1)));
    lo = packh(l0, l1);
    return packh(h0, h1);
}
static __device__ __forceinline__ void upk(uint32_t u, int &a, int &b) {
    a = (int)(short)(u & 0xFFFFu);
    b = ((int)u) >> 16;
}

// 176B rows: 44*i mod 32 covers all banks -> ldmatrix conflict-free
#define ROWB       176u
#define BHI_OFF    0u
#define BLO_OFF    45056u
#define AHI_OFF    90112u
#define ALO_OFF    135168u
#define XSH_OFF    180224u
#define XSL_OFF    185408u
#define CBS_OFF    190592u
#define A1S_OFF    191616u
#define KLUT_OFF   192640u
#define CONV_SMEM  192928

// ---------------------------------------------------------------------------
// Prep: x -> fp16 hi/lo per tile; block 0 additionally splits W (layout-final)
// ---------------------------------------------------------------------------
__global__ void __launch_bounds__(256) prep_kernel(
    const float* __restrict__ x, const float* __restrict__ w)
{
    const int tile = blockIdx.x;           // b*32 + ci
    const float4* src = (const float4*)(x + tile*2048);
    #pragma unroll
    for (int i = 0; i < 2; i++) {
        int idx4 = threadIdx.x + i*256;
        float4 v = src[idx4];
        uint32_t l0, l1;
        uint32_t h0 = packsplit(v.x, v.y, l0);
        uint32_t h1 = packsplit(v.z, v.w, l1);
        *(uint2*)(g_xh + tile*2048 + idx4*4) = make_uint2(h0, h1);
        *(uint2*)(g_xl + tile*2048 + idx4*4) = make_uint2(l0, l1);
    }
    if (blockIdx.x == 0) {
        const int o = threadIdx.x;
        const float4* wr = (const float4*)(w + o*72);
        char* bh = (char*)g_wsplit + o*ROWB;
        char* bl = (char*)g_wsplit + 45056 + o*ROWB;
        #pragma unroll
        for (int q = 0; q < 18; q++) {
            float4 v = wr[q];
            uint32_t l0, l1;
            uint32_t h0 = packsplit(v.x, v.y, l0);
            uint32_t h1 = packsplit(v.z, v.w, l1);
            *(uint2*)(bh + q*8) = make_uint2(h0, h1);
            *(uint2*)(bl + q*8) = make_uint2(l0, l1);
        }
        *(uint4*)(bh + 144) = make_uint4(0,0,0,0);
        *(uint4*)(bh + 160) = make_uint4(0,0,0,0);
        *(uint4*)(bl + 144) = make_uint4(0,0,0,0);
        *(uint4*)(bl + 160) = make_uint4(0,0,0,0);
    }
}

// ---------------------------------------------------------------------------
// Kernel 1: fp16-split mma.sync conv -> int16 votes + iteration-1 logits.
// block = (b, ci), 512 threads / 16 warps. Votes [b][co][ci][p][no].
// ---------------------------------------------------------------------------
__global__ void __launch_bounds__(512, 1) conv_votes_kernel(
    const float* __restrict__ cb, const float* __restrict__ bias)
{
    extern __shared__ char sh[];
    float* cbs = (float*)(sh + CBS_OFF);
    int*   a1s = (int*)(sh + A1S_OFF);
    int*   klut= (int*)(sh + KLUT_OFF);
    const uint32_t smb = smem_u32(sh);

    const int t = threadIdx.x;
    const int wid = t >> 5, lane = t & 31;
    const int b = blockIdx.x >> 5, ci = blockIdx.x & 31;

    {
        const uint4* src = g_wsplit;
        uint4* dst = (uint4*)sh;
        #pragma unroll
        for (int i = 0; i < 11; i++) dst[t + i*512] = src[t + i*512];
    }
    {
        uint32_t* z = (uint32_t*)(sh + XSH_OFF);
        #pragma unroll
        for (int i = 0; i < 6; i++) {
            int idx = t + i*512;
            if (idx < 2592) z[idx] = 0;
        }
    }
    if (t < 256) cbs[t] = cb[t];
    if (t < 72) { int ni = t/9, r = t%9; klut[t] = ni*324 + (r/3)*18 + (r%3); }
    if (t < 32) {
        float pv[8]; float ss = 0.f;
        #pragma unroll
        for (int no = 0; no < 8; no++) {
            float q = rintf(__fmul_rn(bias[t*8+no], 256.f)) * 0.00390625f;
            pv[no] = q; ss = __fadd_rn(ss, __fmul_rn(q, q));
        }
        float n = sqrtf(ss);
        float den = __fadd_rn(1.f, __fmul_rn(n, n));
        #pragma unroll
        for (int no = 0; no < 8; no++) {
            float a = __fdiv_rn(__fmul_rn(pv[no], n), den);
            a1s[t*8+no] = __float2int_rn(__fmul_rn(a, 256.f));
        }
    }
    __syncthreads();

    {
        const __half* xh = g_xh + blockIdx.x*2048;
        const __half* xl = g_xl + blockIdx.x*2048;
        unsigned short* dh = (unsigned short*)(sh + XSH_OFF);
        unsigned short* dl = (unsigned short*)(sh + XSL_OFF);
        #pragma unroll
        for (int i = 0; i < 4; i++) {
            int idx = t + i*512;
            int ni = idx >> 8, rem = idx & 255;
            int dsto = ni*324 + ((rem>>4)+1)*18 + (rem&15) + 1;
            dh[dsto] = __half_as_ushort(xh[idx]);
            dl[dsto] = __half_as_ushort(xl[idx]);
        }
    }
    __syncthreads();
    {
        const int p = t & 255;
        const unsigned short* xsrc = (unsigned short*)(sh + ((t < 256) ? XSH_OFF : XSL_OFF));
        char* dst = sh + ((t < 256) ? AHI_OFF : ALO_OFF) + p*ROWB;
        const int xyb = (p >> 4)*18 + (p & 15);
        #pragma unroll
        for (int q = 0; q < 9; q++) {
            uint32_t u[4];
            #pragma unroll
            for (int j = 0; j < 4; j++) {
                uint32_t v0 = xsrc[klut[q*8 + 2*j]     + xyb];
                uint32_t v1 = xsrc[klut[q*8 + 2*j + 1] + xyb];
                u[j] = v0 | (v1 << 16);
            }
            *(uint4*)(dst + q*16) = make_uint4(u[0], u[1], u[2], u[3]);
        }
        *(uint4*)(dst + 144) = make_uint4(0,0,0,0);
        *(uint4*)(dst + 160) = make_uint4(0,0,0,0);
    }
    __syncthreads();

    const int pbase = (wid & 7)*32;
    const int obase = (wid >> 3)*128;
    const int lane2 = (lane & 3)*2;

    #pragma unroll 1
    for (int pass = 0; pass < 4; pass++) {
        const int otile = obase + pass*32;
        float acc[2][4][4];
        #pragma unroll
        for (int mt = 0; mt < 2; mt++)
            #pragma unroll
            for (int nt = 0; nt < 4; nt++)
                #pragma unroll
                for (int j = 0; j < 4; j++) acc[mt][nt][j] = 0.f;

        #pragma unroll
        for (int kc = 0; kc < 5; kc++) {
            uint32_t ah[2][4], al[2][4];
            #pragma unroll
            for (int mt = 0; mt < 2; mt++) {
                const uint32_t arow = pbase + mt*16 + (lane & 15);
                const uint32_t aoff = arow*ROWB + kc*32 + ((lane >> 4) << 4);
                LDMX4(ah[mt][0], ah[mt][1], ah[mt][2], ah[mt][3], smb + AHI_OFF + aoff);
                LDMX4(al[mt][0], al[mt][1], al[mt][2], al[mt][3], smb + ALO_OFF + aoff);
            }
            uint32_t bh[4][2], bl[4][2];
            #pragma unroll
            for (int g = 0; g < 2; g++) {
                const uint32_t row = otile + g*16 + (lane & 7) + ((lane >> 4) << 3);
                const uint32_t koff = kc*32 + ((lane >> 3) & 1)*16;
                LDMX4(bh[2*g][0], bh[2*g][1], bh[2*g+1][0], bh[2*g+1][1],
                      smb + BHI_OFF + row*ROWB + koff);
                LDMX4(bl[2*g][0], bl[2*g][1], bl[2*g+1][0], bl[2*g+1][1],
                      smb + BLO_OFF + row*ROWB + koff);
            }
            if (kc < 4) {
                #pragma unroll
                for (int mt = 0; mt < 2; mt++)
                    #pragma unroll
                    for (int nt = 0; nt < 4; nt++)
                        MMA16816(acc[mt][nt], ah[mt], bh[nt]);
                #pragma unroll
                for (int mt = 0; mt < 2; mt++)
                    #pragma unroll
                    for (int nt = 0; nt < 4; nt++)
                        MMA16816(acc[mt][nt], ah[mt], bl[nt]);
                #pragma unroll
                for (int mt = 0; mt < 2; mt++)
                    #pragma unroll
                    for (int nt = 0; nt < 4; nt++)
                        MMA16816(acc[mt][nt], al[mt], bh[nt]);
            } else {
                #pragma unroll
                for (int mt = 0; mt < 2; mt++)
                    #pragma unroll
                    for (int nt = 0; nt < 4; nt++)
                        MMA1688(acc[mt][nt], ah[mt][0], ah[mt][1], bh[nt][0]);
                #pragma unroll
                for (int mt = 0; mt < 2; mt++)
                    #pragma unroll
                    for (int nt = 0; nt < 4; nt++)
                        MMA1688(acc[mt][nt], ah[mt][0], ah[mt][1], bl[nt][0]);
                #pragma unroll
                for (int mt = 0; mt < 2; mt++)
                    #pragma unroll
                    for (int nt = 0; nt < 4; nt++)
                        MMA1688(acc[mt][nt], al[mt][0], al[mt][1], bh[nt][0]);
            }
        }

        // epilogue: votes [ci][p][no] (u32 pair stores) + quad-shuffle logit fold
        #pragma unroll
        for (int mt = 0; mt < 2; mt++) {
            const int p0 = pbase + mt*16 + (lane >> 2);
            #pragma unroll
            for (int nt = 0; nt < 4; nt++) {
                const int o = otile + nt*8 + lane2;     // no = lane2 (even), co = o>>3
                const float cb0 = cbs[o], cb1 = cbs[o+1];
                int v0 = __float2int_rn((acc[mt][nt][0] + cb0) * 256.f);
                int v1 = __float2int_rn((acc[mt][nt][1] + cb1) * 256.f);
                int v2 = __float2int_rn((acc[mt][nt][2] + cb0) * 256.f);
                int v3 = __float2int_rn((acc[mt][nt][3] + cb1) * 256.f);
                short* vb = g_votes + ((size_t)b << 21) + ((o >> 3)*32 + ci)*2048;
                *(uint32_t*)(vb + p0*8 + lane2)       = (v0 & 0xFFFF) | ((uint32_t)v1 << 16);
                *(uint32_t*)(vb + (p0 + 8)*8 + lane2) = (v2 & 0xFFFF) | ((uint32_t)v3 << 16);
                int s0 = a1s[o]*v0 + a1s[o+1]*v1;
                int s1 = a1s[o]*v2 + a1s[o+1]*v3;
                s0 += __shfl_xor_sync(0xffffffffu, s0, 1);
                s0 += __shfl_xor_sync(0xffffffffu, s0, 2);
                s1 += __shfl_xor_sync(0xffffffffu, s1, 1);
                s1 += __shfl_xor_sync(0xffffffffu, s1, 2);
                if ((lane & 3) == 0) {
                    float* lb = g_logits + ((b*32 + ci)*32 + (o >> 3))*256;
                    lb[p0]     = rintf((float)s0 * 0.00390625f) * 0.00390625f;
                    lb[p0 + 8] = rintf((float)s1 * 0.00390625f) * 0.00390625f;
                }
            }
        }
    }
}

// ---------------------------------------------------------------------------
// Kernel 2: softmax stats per (b, ci) over 8192 logits (+ r>=1 threshold)
// ---------------------------------------------------------------------------
__global__ void __launch_bounds__(256) softmax_kernel()
{
    const int row = blockIdx.x;
    const float* lp = g_logits + row*8192;
    const int t = threadIdx.x;
    float fl[32];
    #pragma unroll
    for (int i = 0; i < 32; i++) fl[i] = lp[i*256 + t];
    float m = fl[0];
    #pragma unroll
    for (int i = 1; i < 32; i++) m = fmaxf(m, fl[i]);
    __shared__ float red[8];
    #pragma unroll
    for (int off = 16; off; off >>= 1) m = fmaxf(m, __shfl_xor_sync(0xffffffffu, m, off));
    if ((t & 31) == 0) red[t >> 5] = m;
    __syncthreads();
    float M = red[0];
    #pragma unroll
    for (int i = 1; i < 8; i++) M = fmaxf(M, red[i]);
    __syncthreads();
    float s = 0.f;
    #pragma unroll
    for (int i = 0; i < 32; i++) s += expf(fl[i] - M);
    #pragma unroll
    for (int off = 16; off; off >>= 1) s += __shfl_xor_sync(0xffffffffu, s, off);
    if ((t & 31) == 0) red[t >> 5] = s;
    __syncthreads();
    if (t == 0) {
        float S = red[0];
        for (int i = 1; i < 8; i++) S += red[i];
        g_smax[row] = M;
        g_ssum[row] = S;
        // r >= 1 requires 256*e^(lv-M)/S > 0.5  <=>  lv >= M + ln(S/512).
        g_thr[row] = M + logf(S * 0.001953125f) - 1e-3f;
    }
}

// ---------------------------------------------------------------------------
// Kernel 3: fused routing iteration. block = (bco, ph); 256 threads =
// (p 0..127) x (c-half 0..1). Each half walks 16 c's; exact-int partial S
// reduced via smem (order-invariant) -> bit-identical results. out written
// only on the last iteration (iter-2's activation is consumed solely as ai).
// ---------------------------------------------------------------------------
__global__ void __launch_bounds__(256) route_kernel(
    const float* __restrict__ bias, float* __restrict__ out, int last)
{
    __shared__ float smaxs[32], ssums[32], sthr[32], sb[8];
    __shared__ int sS[2][128][8];    // partial S per (chalf, p, no)
    __shared__ int sai[128][8];      // activation ints per (p, no)

    const int t   = threadIdx.x;
    const int th  = t & 127;         // p index within half
    const int chh = t >> 7;          // c-half (0: c 0..15, 1: c 16..31)
    const int blk = blockIdx.x;
    const int bco = blk >> 1, ph = blk & 1;
    const int b   = bco >> 5, co = bco & 31;

    if (t < 32) {
        smaxs[t] = g_smax[b*32 + t];
        ssums[t] = g_ssum[b*32 + t];
        sthr[t]  = g_thr[b*32 + t];
    }
    if (t < 8)  sb[t] = bias[co*8 + t];
    __syncthreads();

    const uint4* vbase = (const uint4*)(g_votes + (size_t)bco*65536) + ph*128 + th;
    const float* lgp = g_logits + (size_t)(b*32 + chh*16)*8192 + co*256 + ph*128 + th;

    float l[16];
    int S[8] = {0,0,0,0,0,0,0,0};
    #pragma unroll
    for (int i = 0; i < 16; i++) {
        const int c = chh*16 + i;
        float lv = lgp[i*8192];
        l[i] = lv;
        if (lv >= sthr[c]) {      // only here can r >= 1 (guaranteed otherwise 0)
            float e = expf(lv - smaxs[c]);
            int r = __float2int_rn(__fmul_rn(__fdiv_rn(e, ssums[c]), 256.f));
            if (r) {
                uint4 vv = vbase[c*256];
                int e0, e1;
                upk(vv.x, e0, e1); S[0] += r*e0; S[1] += r*e1;
                upk(vv.y, e0, e1); S[2] += r*e0; S[3] += r*e1;
                upk(vv.z, e0, e1); S[4] += r*e0; S[5] += r*e1;
                upk(vv.w, e0, e1); S[6] += r*e0; S[7] += r*e1;
            }
        }
    }
    #pragma unroll
    for (int no = 0; no < 8; no++) sS[chh][th][no] = S[no];
    __syncthreads();

    if (chh == 0) {
        float pq[8]; float ss = 0.f;
        #pragma unroll
        for (int no = 0; no < 8; no++) {
            int St = sS[0][th][no] + sS[1][th][no];      // exact int
            float pre = __fadd_rn(__fmul_rn((float)St, 1.52587890625e-05f), sb[no]);
            float q = rintf(__fmul_rn(pre, 256.f)) * 0.00390625f;
            pq[no] = q; ss = __fadd_rn(ss, __fmul_rn(q, q));
        }
        float n   = sqrtf(ss);
        float den = __fadd_rn(1.f, __fmul_rn(n, n));
        #pragma unroll
        for (int no = 0; no < 8; no++) {
            float a = __fdiv_rn(__fmul_rn(pq[no], n), den);
            int q = __float2int_rn(__fmul_rn(a, 256.f));
            sai[th][no] = q;
            if (last)
                out[(bco*8 + no)*256 + ph*128 + th] = (float)q * 0.00390625f;
        }
    }
    __syncthreads();

    if (!last) {
        int ai[8];
        #pragma unroll
        for (int no = 0; no < 8; no++) ai[no] = sai[th][no];
        float* lw = g_logits + (size_t)(b*32 + chh*16)*8192 + co*256 + ph*128 + th;
        #pragma unroll
        for (int i = 0; i < 16; i++) {
            const int c = chh*16 + i;
            uint4 vv = vbase[c*256];
            int e0, e1, m = 0;
            upk(vv.x, e0, e1); m += ai[0]*e0 + ai[1]*e1;
            upk(vv.y, e0, e1); m += ai[2]*e0 + ai[3]*e1;
            upk(vv.z, e0, e1); m += ai[4]*e0 + ai[5]*e1;
            upk(vv.w, e0, e1); m += ai[6]*e0 + ai[7]*e1;
            float lg = __fadd_rn(l[i], __fmul_rn((float)m, 1.52587890625e-05f));
            lw[i*8192] = rintf(__fmul_rn(lg, 256.f)) * 0.00390625f;
        }
    }
}

// ---------------------------------------------------------------------------
extern "C" void kernel_launch(void* const* d_in, const int* in_sizes, int n_in,
                              void* d_out, int out_size)
{
    const float* x    = (const float*)d_in[0];
    const float* w    = (const float*)d_in[1];
    const float* cb   = (const float*)d_in[2];
    const float* bias = (const float*)d_in[3];
    float* out = (float*)d_out;
    (void)in_sizes; (void)n_in; (void)out_size;

    cudaFuncSetAttribute(conv_votes_kernel, cudaFuncAttributeMaxDynamicSharedMemorySize, CONV_SMEM);

    prep_kernel<<<1024, 256>>>(x, w);                         // launch 1 (W + x split)
    conv_votes_kernel<<<1024, 512, CONV_SMEM>>>(cb, bias);    // launch 2 (+ iter 1 folded)
    softmax_kernel<<<1024, 256>>>();                          // launch 3 (iteration 2)
    route_kernel<<<2048, 256>>>(bias, out, 0);                // launch 4 -> profiled
    softmax_kernel<<<1024, 256>>>();                          // iteration 3
    route_kernel<<<2048, 256>>>(bias, out, 1);
}

// round 17
// speedup vs baseline: 1.7810x; 1.1585x over previous
#include <cuda_runtime.h>
#include <cuda_fp16.h>
#include <cstdint>

#define BSZ 32
#define CIc 32
#define PP  256

__device__ short g_votes[BSZ*32*CIc*8*PP];   // [b][co][ci][p][no], value*256 (exact)
__device__ float g_logits[BSZ*CIc*32*PP];    // [b][ci][co][p]
__device__ float g_smax[BSZ*CIc];
__device__ float g_ssum[BSZ*CIc];
__device__ float g_thr[BSZ*CIc];             // r>=1 threshold: M + ln(S/512) - margin
__device__ uint4  g_wsplit[5632];            // W fp16 hi[0..45056) lo[45056..90112), 176B rows
__device__ __half g_xh[BSZ*CIc*2048];        // x fp16 hi
__device__ __half g_xl[BSZ*CIc*2048];        // x fp16 lo

// ---------------- helpers ----------------
static __device__ __forceinline__ uint32_t smem_u32(const void* p) {
    uint32_t a;
    asm("{ .reg .u64 t; cvta.to.shared.u64 t, %1; cvt.u32.u64 %0, t; }" : "=r"(a) : "l"(p));
    return a;
}

#define MMA16816(d, a, b) \
    asm volatile("mma.sync.aligned.m16n8k16.row.col.f32.f16.f16.f32 " \
        "{%0,%1,%2,%3}, {%4,%5,%6,%7}, {%8,%9}, {%0,%1,%2,%3};" \
        : "+f"((d)[0]), "+f"((d)[1]), "+f"((d)[2]), "+f"((d)[3]) \
        : "r"((a)[0]), "r"((a)[1]), "r"((a)[2]), "r"((a)[3]), "r"((b)[0]), "r"((b)[1]))

#define MMA1688(d, a0, a1, b0) \
    asm volatile("mma.sync.aligned.m16n8k8.row.col.f32.f16.f16.f32 " \
        "{%0,%1,%2,%3}, {%4,%5}, {%6}, {%0,%1,%2,%3};" \
        : "+f"((d)[0]), "+f"((d)[1]), "+f"((d)[2]), "+f"((d)[3]) \
        : "r"(a0), "r"(a1), "r"(b0))

#define LDMX4(r0, r1, r2, r3, addr) \
    asm volatile("ldmatrix.sync.aligned.m8n8.x4.shared.b16 {%0,%1,%2,%3}, [%4];" \
        : "=r"(r0), "=r"(r1), "=r"(r2), "=r"(r3) : "r"(addr))

static __device__ __forceinline__ uint32_t packh(__half a, __half b) {
    return (uint32_t)__half_as_ushort(a) | ((uint32_t)__half_as_ushort(b) << 16);
}
static __device__ __forceinline__ uint32_t packsplit(float f0, float f1, uint32_t &lo) {
    __half h0 = __float2half_rn(f0), h1 = __float2half_rn(f1);
    __half l0 = __float2half_rn(__fsub_rn(f0, __half2float(h0)));
    __half l1 = __float2half_rn(__fsub_rn(f1, __half2float(h1)));
    lo = packh(l0, l1);
    return packh(h0, h1);
}
static __device__ __forceinline__ void upk(uint32_t u, int &a, int &b) {
    a = (int)(short)(u & 0xFFFFu);
    b = ((int)u) >> 16;
}

// 176B rows: 44*i mod 32 covers all banks -> ldmatrix conflict-free
#define ROWB       176u
#define BHI_OFF    0u
#define BLO_OFF    45056u
#define AHI_OFF    90112u
#define ALO_OFF    135168u
#define XSH_OFF    180224u
#define XSL_OFF    185408u
#define CBS_OFF    190592u
#define A1S_OFF    191616u
#define KLUT_OFF   192640u
#define CONV_SMEM  192928

// ---------------------------------------------------------------------------
// Prep: x -> fp16 hi/lo per tile; block 0 additionally splits W (layout-final)
// ---------------------------------------------------------------------------
__global__ void __launch_bounds__(256) prep_kernel(
    const float* __restrict__ x, const float* __restrict__ w)
{
    const int tile = blockIdx.x;           // b*32 + ci
    const float4* src = (const float4*)(x + tile*2048);
    #pragma unroll
    for (int i = 0; i < 2; i++) {
        int idx4 = threadIdx.x + i*256;
        float4 v = src[idx4];
        uint32_t l0, l1;
        uint32_t h0 = packsplit(v.x, v.y, l0);
        uint32_t h1 = packsplit(v.z, v.w, l1);
        *(uint2*)(g_xh + tile*2048 + idx4*4) = make_uint2(h0, h1);
        *(uint2*)(g_xl + tile*2048 + idx4*4) = make_uint2(l0, l1);
    }
    if (blockIdx.x == 0) {
        const int o = threadIdx.x;
        const float4* wr = (const float4*)(w + o*72);
        char* bh = (char*)g_wsplit + o*ROWB;
        char* bl = (char*)g_wsplit + 45056 + o*ROWB;
        #pragma unroll
        for (int q = 0; q < 18; q++) {
            float4 v = wr[q];
            uint32_t l0, l1;
            uint32_t h0 = packsplit(v.x, v.y, l0);
            uint32_t h1 = packsplit(v.z, v.w, l1);
            *(uint2*)(bh + q*8) = make_uint2(h0, h1);
            *(uint2*)(bl + q*8) = make_uint2(l0, l1);
        }
        *(uint4*)(bh + 144) = make_uint4(0,0,0,0);
        *(uint4*)(bh + 160) = make_uint4(0,0,0,0);
        *(uint4*)(bl + 144) = make_uint4(0,0,0,0);
        *(uint4*)(bl + 160) = make_uint4(0,0,0,0);
    }
}

// ---------------------------------------------------------------------------
// Kernel 1: fp16-split mma.sync conv -> int16 votes + iteration-1 logits.
// block = (b, ci), 512 threads / 16 warps. Votes [b][co][ci][p][no].
// ---------------------------------------------------------------------------
__global__ void __launch_bounds__(512, 1) conv_votes_kernel(
    const float* __restrict__ cb, const float* __restrict__ bias)
{
    extern __shared__ char sh[];
    float* cbs = (float*)(sh + CBS_OFF);
    int*   a1s = (int*)(sh + A1S_OFF);
    int*   klut= (int*)(sh + KLUT_OFF);
    const uint32_t smb = smem_u32(sh);

    const int t = threadIdx.x;
    const int wid = t >> 5, lane = t & 31;
    const int b = blockIdx.x >> 5, ci = blockIdx.x & 31;

    {
        const uint4* src = g_wsplit;
        uint4* dst = (uint4*)sh;
        #pragma unroll
        for (int i = 0; i < 11; i++) dst[t + i*512] = src[t + i*512];
    }
    {
        uint32_t* z = (uint32_t*)(sh + XSH_OFF);
        #pragma unroll
        for (int i = 0; i < 6; i++) {
            int idx = t + i*512;
            if (idx < 2592) z[idx] = 0;
        }
    }
    if (t < 256) cbs[t] = cb[t];
    if (t < 72) { int ni = t/9, r = t%9; klut[t] = ni*324 + (r/3)*18 + (r%3); }
    if (t < 32) {
        float pv[8]; float ss = 0.f;
        #pragma unroll
        for (int no = 0; no < 8; no++) {
            float q = rintf(__fmul_rn(bias[t*8+no], 256.f)) * 0.00390625f;
            pv[no] = q; ss = __fadd_rn(ss, __fmul_rn(q, q));
        }
        float n = sqrtf(ss);
        float den = __fadd_rn(1.f, __fmul_rn(n, n));
        #pragma unroll
        for (int no = 0; no < 8; no++) {
            float a = __fdiv_rn(__fmul_rn(pv[no], n), den);
            a1s[t*8+no] = __float2int_rn(__fmul_rn(a, 256.f));
        }
    }
    __syncthreads();

    {
        const __half* xh = g_xh + blockIdx.x*2048;
        const __half* xl = g_xl + blockIdx.x*2048;
        unsigned short* dh = (unsigned short*)(sh + XSH_OFF);
        unsigned short* dl = (unsigned short*)(sh + XSL_OFF);
        #pragma unroll
        for (int i = 0; i < 4; i++) {
            int idx = t + i*512;
            int ni = idx >> 8, rem = idx & 255;
            int dsto = ni*324 + ((rem>>4)+1)*18 + (rem&15) + 1;
            dh[dsto] = __half_as_ushort(xh[idx]);
            dl[dsto] = __half_as_ushort(xl[idx]);
        }
    }
    __syncthreads();
    {
        const int p = t & 255;
        const unsigned short* xsrc = (unsigned short*)(sh + ((t < 256) ? XSH_OFF : XSL_OFF));
        char* dst = sh + ((t < 256) ? AHI_OFF : ALO_OFF) + p*ROWB;
        const int xyb = (p >> 4)*18 + (p & 15);
        #pragma unroll
        for (int q = 0; q < 9; q++) {
            uint32_t u[4];
            #pragma unroll
            for (int j = 0; j < 4; j++) {
                uint32_t v0 = xsrc[klut[q*8 + 2*j]     + xyb];
                uint32_t v1 = xsrc[klut[q*8 + 2*j + 1] + xyb];
                u[j] = v0 | (v1 << 16);
            }
            *(uint4*)(dst + q*16) = make_uint4(u[0], u[1], u[2], u[3]);
        }
        *(uint4*)(dst + 144) = make_uint4(0,0,0,0);
        *(uint4*)(dst + 160) = make_uint4(0,0,0,0);
    }
    __syncthreads();

    const int pbase = (wid & 7)*32;
    const int obase = (wid >> 3)*128;
    const int lane2 = (lane & 3)*2;

    #pragma unroll 1
    for (int pass = 0; pass < 4; pass++) {
        const int otile = obase + pass*32;
        float acc[2][4][4];
        #pragma unroll
        for (int mt = 0; mt < 2; mt++)
            #pragma unroll
            for (int nt = 0; nt < 4; nt++)
                #pragma unroll
                for (int j = 0; j < 4; j++) acc[mt][nt][j] = 0.f;

        #pragma unroll
        for (int kc = 0; kc < 5; kc++) {
            uint32_t ah[2][4], al[2][4];
            #pragma unroll
            for (int mt = 0; mt < 2; mt++) {
                const uint32_t arow = pbase + mt*16 + (lane & 15);
                const uint32_t aoff = arow*ROWB + kc*32 + ((lane >> 4) << 4);
                LDMX4(ah[mt][0], ah[mt][1], ah[mt][2], ah[mt][3], smb + AHI_OFF + aoff);
                LDMX4(al[mt][0], al[mt][1], al[mt][2], al[mt][3], smb + ALO_OFF + aoff);
            }
            uint32_t bh[4][2], bl[4][2];
            #pragma unroll
            for (int g = 0; g < 2; g++) {
                const uint32_t row = otile + g*16 + (lane & 7) + ((lane >> 4) << 3);
                const uint32_t koff = kc*32 + ((lane >> 3) & 1)*16;
                LDMX4(bh[2*g][0], bh[2*g][1], bh[2*g+1][0], bh[2*g+1][1],
                      smb + BHI_OFF + row*ROWB + koff);
                LDMX4(bl[2*g][0], bl[2*g][1], bl[2*g+1][0], bl[2*g+1][1],
                      smb + BLO_OFF + row*ROWB + koff);
            }
            if (kc < 4) {
                #pragma unroll
                for (int mt = 0; mt < 2; mt++)
                    #pragma unroll
                    for (int nt = 0; nt < 4; nt++)
                        MMA16816(acc[mt][nt], ah[mt], bh[nt]);
                #pragma unroll
                for (int mt = 0; mt < 2; mt++)
                    #pragma unroll
                    for (int nt = 0; nt < 4; nt++)
                        MMA16816(acc[mt][nt], ah[mt], bl[nt]);
                #pragma unroll
                for (int mt = 0; mt < 2; mt++)
                    #pragma unroll
                    for (int nt = 0; nt < 4; nt++)
                        MMA16816(acc[mt][nt], al[mt], bh[nt]);
            } else {
                #pragma unroll
                for (int mt = 0; mt < 2; mt++)
                    #pragma unroll
                    for (int nt = 0; nt < 4; nt++)
                        MMA1688(acc[mt][nt], ah[mt][0], ah[mt][1], bh[nt][0]);
                #pragma unroll
                for (int mt = 0; mt < 2; mt++)
                    #pragma unroll
                    for (int nt = 0; nt < 4; nt++)
                        MMA1688(acc[mt][nt], ah[mt][0], ah[mt][1], bl[nt][0]);
                #pragma unroll
                for (int mt = 0; mt < 2; mt++)
                    #pragma unroll
                    for (int nt = 0; nt < 4; nt++)
                        MMA1688(acc[mt][nt], al[mt][0], al[mt][1], bh[nt][0]);
            }
        }

        // epilogue: votes [ci][p][no] (u32 pair stores) + quad-shuffle logit fold
        #pragma unroll
        for (int mt = 0; mt < 2; mt++) {
            const int p0 = pbase + mt*16 + (lane >> 2);
            #pragma unroll
            for (int nt = 0; nt < 4; nt++) {
                const int o = otile + nt*8 + lane2;     // no = lane2 (even), co = o>>3
                const float cb0 = cbs[o], cb1 = cbs[o+1];
                int v0 = __float2int_rn((acc[mt][nt][0] + cb0) * 256.f);
                int v1 = __float2int_rn((acc[mt][nt][1] + cb1) * 256.f);
                int v2 = __float2int_rn((acc[mt][nt][2] + cb0) * 256.f);
                int v3 = __float2int_rn((acc[mt][nt][3] + cb1) * 256.f);
                short* vb = g_votes + ((size_t)b << 21) + ((o >> 3)*32 + ci)*2048;
                *(uint32_t*)(vb + p0*8 + lane2)       = (v0 & 0xFFFF) | ((uint32_t)v1 << 16);
                *(uint32_t*)(vb + (p0 + 8)*8 + lane2) = (v2 & 0xFFFF) | ((uint32_t)v3 << 16);
                int s0 = a1s[o]*v0 + a1s[o+1]*v1;
                int s1 = a1s[o]*v2 + a1s[o+1]*v3;
                s0 += __shfl_xor_sync(0xffffffffu, s0, 1);
                s0 += __shfl_xor_sync(0xffffffffu, s0, 2);
                s1 += __shfl_xor_sync(0xffffffffu, s1, 1);
                s1 += __shfl_xor_sync(0xffffffffu, s1, 2);
                if ((lane & 3) == 0) {
                    float* lb = g_logits + ((b*32 + ci)*32 + (o >> 3))*256;
                    lb[p0]     = rintf((float)s0 * 0.00390625f) * 0.00390625f;
                    lb[p0 + 8] = rintf((float)s1 * 0.00390625f) * 0.00390625f;
                }
            }
        }
    }
}

// ---------------------------------------------------------------------------
// Kernel 2: softmax stats per (b, ci) over 8192 logits (+ r>=1 threshold)
// ---------------------------------------------------------------------------
__global__ void __launch_bounds__(256) softmax_kernel()
{
    const int row = blockIdx.x;
    const float* lp = g_logits + row*8192;
    const int t = threadIdx.x;
    float fl[32];
    #pragma unroll
    for (int i = 0; i < 32; i++) fl[i] = lp[i*256 + t];
    float m = fl[0];
    #pragma unroll
    for (int i = 1; i < 32; i++) m = fmaxf(m, fl[i]);
    __shared__ float red[8];
    #pragma unroll
    for (int off = 16; off; off >>= 1) m = fmaxf(m, __shfl_xor_sync(0xffffffffu, m, off));
    if ((t & 31) == 0) red[t >> 5] = m;
    __syncthreads();
    float M = red[0];
    #pragma unroll
    for (int i = 1; i < 8; i++) M = fmaxf(M, red[i]);
    __syncthreads();
    float s = 0.f;
    #pragma unroll
    for (int i = 0; i < 32; i++) s += expf(fl[i] - M);
    #pragma unroll
    for (int off = 16; off; off >>= 1) s += __shfl_xor_sync(0xffffffffu, s, off);
    if ((t & 31) == 0) red[t >> 5] = s;
    __syncthreads();
    if (t == 0) {
        float S = red[0];
        for (int i = 1; i < 8; i++) S += red[i];
        g_smax[row] = M;
        g_ssum[row] = S;
        // r >= 1 requires 256*e^(lv-M)/S > 0.5  <=>  lv >= M + ln(S/512).
        g_thr[row] = M + logf(S * 0.001953125f) - 1e-3f;
    }
}

// ---------------------------------------------------------------------------
// Kernel 3: fused routing iteration. block = (bco, ph); 256 threads =
// (p 0..127) x (c-half 0..1). Loads batched for MLP: 16 logits prefetched
// up-front; distance loop prefetches 4 vote uint4s per chunk. Exact-int
// partial S via smem (order-invariant) -> bit-identical. out written only
// on the last iteration.
// ---------------------------------------------------------------------------
__global__ void __launch_bounds__(256) route_kernel(
    const float* __restrict__ bias, float* __restrict__ out, int last)
{
    __shared__ float smaxs[32], ssums[32], sthr[32], sb[8];
    __shared__ int sS[2][128][8];    // partial S per (chalf, p, no)
    __shared__ int sai[128][8];      // activation ints per (p, no)

    const int t   = threadIdx.x;
    const int th  = t & 127;         // p index within half
    const int chh = t >> 7;          // c-half (0: c 0..15, 1: c 16..31)
    const int blk = blockIdx.x;
    const int bco = blk >> 1, ph = blk & 1;
    const int b   = bco >> 5, co = bco & 31;

    if (t < 32) {
        smaxs[t] = g_smax[b*32 + t];
        ssums[t] = g_ssum[b*32 + t];
        sthr[t]  = g_thr[b*32 + t];
    }
    if (t < 8)  sb[t] = bias[co*8 + t];
    __syncthreads();

    const uint4* vbase = (const uint4*)(g_votes + (size_t)bco*65536) + ph*128 + th;
    const float* lgp = g_logits + (size_t)(b*32 + chh*16)*8192 + co*256 + ph*128 + th;

    // batched logits prefetch: 16 independent loads in flight (MLP=16)
    float l[16];
    #pragma unroll
    for (int i = 0; i < 16; i++) l[i] = lgp[i*8192];

    int S[8] = {0,0,0,0,0,0,0,0};
    #pragma unroll
    for (int i = 0; i < 16; i++) {
        const int c = chh*16 + i;
        if (l[i] >= sthr[c]) {    // only here can r >= 1 (guaranteed otherwise 0)
            float e = expf(l[i] - smaxs[c]);
            int r = __float2int_rn(__fmul_rn(__fdiv_rn(e, ssums[c]), 256.f));
            if (r) {
                uint4 vv = vbase[c*256];
                int e0, e1;
                upk(vv.x, e0, e1); S[0] += r*e0; S[1] += r*e1;
                upk(vv.y, e0, e1); S[2] += r*e0; S[3] += r*e1;
                upk(vv.z, e0, e1); S[4] += r*e0; S[5] += r*e1;
                upk(vv.w, e0, e1); S[6] += r*e0; S[7] += r*e1;
            }
        }
    }
    #pragma unroll
    for (int no = 0; no < 8; no++) sS[chh][th][no] = S[no];
    __syncthreads();

    if (chh == 0) {
        float pq[8]; float ss = 0.f;
        #pragma unroll
        for (int no = 0; no < 8; no++) {
            int St = sS[0][th][no] + sS[1][th][no];      // exact int
            float pre = __fadd_rn(__fmul_rn((float)St, 1.52587890625e-05f), sb[no]);
            float q = rintf(__fmul_rn(pre, 256.f)) * 0.00390625f;
            pq[no] = q; ss = __fadd_rn(ss, __fmul_rn(q, q));
        }
        float n   = sqrtf(ss);
        float den = __fadd_rn(1.f, __fmul_rn(n, n));
        #pragma unroll
        for (int no = 0; no < 8; no++) {
            float a = __fdiv_rn(__fmul_rn(pq[no], n), den);
            int q = __float2int_rn(__fmul_rn(a, 256.f));
            sai[th][no] = q;
            if (last)
                out[(bco*8 + no)*256 + ph*128 + th] = (float)q * 0.00390625f;
        }
    }
    __syncthreads();

    if (!last) {
        int ai[8];
        #pragma unroll
        for (int no = 0; no < 8; no++) ai[no] = sai[th][no];
        float* lw = g_logits + (size_t)(b*32 + chh*16)*8192 + co*256 + ph*128 + th;
        // chunked: prefetch 4 vote vectors (MLP=4), then unpack/accumulate/store
        #pragma unroll
        for (int cc = 0; cc < 16; cc += 4) {
            uint4 vv[4];
            #pragma unroll
            for (int j = 0; j < 4; j++)
                vv[j] = vbase[(chh*16 + cc + j)*256];
            #pragma unroll
            for (int j = 0; j < 4; j++) {
                int e0, e1, m = 0;
                upk(vv[j].x, e0, e1); m += ai[0]*e0 + ai[1]*e1;
                upk(vv[j].y, e0, e1); m += ai[2]*e0 + ai[3]*e1;
                upk(vv[j].z, e0, e1); m += ai[4]*e0 + ai[5]*e1;
                upk(vv[j].w, e0, e1); m += ai[6]*e0 + ai[7]*e1;
                float lg = __fadd_rn(l[cc + j], __fmul_rn((float)m, 1.52587890625e-05f));
                lw[(cc + j)*8192] = rintf(__fmul_rn(lg, 256.f)) * 0.00390625f;
            }
        }
    }
}

// ---------------------------------------------------------------------------
extern "C" void kernel_launch(void* const* d_in, const int* in_sizes, int n_in,
                              void* d_out, int out_size)
{
    const float* x    = (const float*)d_in[0];
    const float* w    = (const float*)d_in[1];
    const float* cb   = (const float*)d_in[2];
    const float* bias = (const float*)d_in[3];
    float* out = (float*)d_out;
    (void)in_sizes; (void)n_in; (void)out_size;

    cudaFuncSetAttribute(conv_votes_kernel, cudaFuncAttributeMaxDynamicSharedMemorySize, CONV_SMEM);

    prep_kernel<<<1024, 256>>>(x, w);                         // launch 1 (W + x split)
    conv_votes_kernel<<<1024, 512, CONV_SMEM>>>(cb, bias);    // launch 2 (+ iter 1 folded)
    softmax_kernel<<<1024, 256>>>();                          // launch 3 (iteration 2)
    route_kernel<<<2048, 256>>>(bias, out, 0);                // launch 4 -> profiled
    softmax_kernel<<<1024, 256>>>();                          // iteration 3
    route_kernel<<<2048, 256>>>(bias, out, 1);
}